// round 3
// baseline (speedup 1.0000x reference)
#include <cuda_runtime.h>
#include <math.h>

// ---------------------------------------------------------------------------
// GAT, 3 layers, single head.
//   N = 100000 nodes, E = 1200000 edges (+N self loops), dims 64->64->64->40
// edge_index arrives as int32 (JAX x64 disabled downgrades int64 -> int32).
// NOTE: online-softmax sentinel must be FINITE (-1e30f), not -inf, or the
// warp-combine produces exp(-inf - -inf) = NaN on empty lanes.
// ---------------------------------------------------------------------------

#define MAXN 100000
#define MAXE 1300000   // E + N self loops
#define NEG_BIG (-1.0e30f)

__device__ float g_hA[(size_t)MAXN * 64];
__device__ float g_hB[(size_t)MAXN * 64];
__device__ float g_as[MAXN];
__device__ float g_ad[MAXN];
__device__ int   g_deg[MAXN];
__device__ int   g_off[MAXN + 1];
__device__ int   g_cur[MAXN];
__device__ int   g_csr[MAXE];

// ---------------------------------------------------------------------------
// CSR build
// ---------------------------------------------------------------------------

__global__ void zero_deg_kernel(int N) {
    int i = blockIdx.x * blockDim.x + threadIdx.x;
    if (i < N) g_deg[i] = 0;
}

__global__ void count_edges_kernel(const int* __restrict__ ei, int E, int N) {
    int i = blockIdx.x * blockDim.x + threadIdx.x;
    int EL = E + N;
    if (i >= EL) return;
    int d = (i < E) ? ei[E + i] : (i - E);
    if (d >= 0 && d < N) atomicAdd(&g_deg[d], 1);
}

__global__ void scan_offsets_kernel(int N) {
    __shared__ int sums[1024];
    int tid = threadIdx.x;
    int chunk = (N + 1023) >> 10;
    int st = tid * chunk;
    int en = min(st + chunk, N);
    int local = 0;
    for (int i = st; i < en; i++) local += g_deg[i];
    sums[tid] = local;
    __syncthreads();
    for (int off = 1; off < 1024; off <<= 1) {
        int v = (tid >= off) ? sums[tid - off] : 0;
        __syncthreads();
        sums[tid] += v;
        __syncthreads();
    }
    int run = sums[tid] - local;  // exclusive prefix
    for (int i = st; i < en; i++) {
        g_off[i] = run;
        g_cur[i] = run;
        run += g_deg[i];
    }
    if (tid == 1023) g_off[N] = sums[1023];
}

__global__ void scatter_edges_kernel(const int* __restrict__ ei, int E, int N) {
    int i = blockIdx.x * blockDim.x + threadIdx.x;
    int EL = E + N;
    if (i >= EL) return;
    int s, d;
    if (i < E) {
        s = ei[i];
        d = ei[E + i];
    } else {
        s = d = i - E;
    }
    if (s < 0 || s >= N || d < 0 || d >= N) return;
    int p = atomicAdd(&g_cur[d], 1);
    g_csr[p] = s;
}

// ---------------------------------------------------------------------------
// GEMM with fused attention-coefficient epilogue:
//   h[row] = x[row] @ W ;  g_as[row] = h[row].a_src ; g_ad[row] = h[row].a_dst
// ---------------------------------------------------------------------------

template <int DIN, int DOUT>
__global__ __launch_bounds__(128)
void gemm_alpha_kernel(const float* __restrict__ x,
                       const float* __restrict__ W,
                       const float* __restrict__ a_src,
                       const float* __restrict__ a_dst,
                       float* __restrict__ h,
                       int N) {
    __shared__ float Ws[DIN * DOUT];
    __shared__ float as_s[DOUT];
    __shared__ float ad_s[DOUT];
    for (int i = threadIdx.x; i < DIN * DOUT; i += blockDim.x) Ws[i] = W[i];
    for (int i = threadIdx.x; i < DOUT; i += blockDim.x) {
        as_s[i] = a_src[i];
        ad_s[i] = a_dst[i];
    }
    __syncthreads();

    int row = blockIdx.x * blockDim.x + threadIdx.x;
    if (row >= N) return;

    float acc[DOUT];
#pragma unroll
    for (int j = 0; j < DOUT; j++) acc[j] = 0.0f;

    const float4* x4 = (const float4*)(x + (size_t)row * DIN);
    const float4* Ws4 = (const float4*)Ws;

#pragma unroll 1
    for (int k4 = 0; k4 < DIN / 4; k4++) {
        float4 xv = __ldg(&x4[k4]);
        int k = k4 * 4;
#pragma unroll
        for (int j4 = 0; j4 < DOUT / 4; j4++) {
            float4 w0 = Ws4[(k + 0) * (DOUT / 4) + j4];
            float4 w1 = Ws4[(k + 1) * (DOUT / 4) + j4];
            float4 w2 = Ws4[(k + 2) * (DOUT / 4) + j4];
            float4 w3 = Ws4[(k + 3) * (DOUT / 4) + j4];
            acc[j4 * 4 + 0] += xv.x * w0.x + xv.y * w1.x + xv.z * w2.x + xv.w * w3.x;
            acc[j4 * 4 + 1] += xv.x * w0.y + xv.y * w1.y + xv.z * w2.y + xv.w * w3.y;
            acc[j4 * 4 + 2] += xv.x * w0.z + xv.y * w1.z + xv.z * w2.z + xv.w * w3.z;
            acc[j4 * 4 + 3] += xv.x * w0.w + xv.y * w1.w + xv.z * w2.w + xv.w * w3.w;
        }
    }

    float ds = 0.0f, dd = 0.0f;
    float4* h4 = (float4*)(h + (size_t)row * DOUT);
#pragma unroll
    for (int j4 = 0; j4 < DOUT / 4; j4++) {
        float4 v;
        v.x = acc[j4 * 4 + 0];
        v.y = acc[j4 * 4 + 1];
        v.z = acc[j4 * 4 + 2];
        v.w = acc[j4 * 4 + 3];
        h4[j4] = v;
        ds += v.x * as_s[j4 * 4 + 0] + v.y * as_s[j4 * 4 + 1] +
              v.z * as_s[j4 * 4 + 2] + v.w * as_s[j4 * 4 + 3];
        dd += v.x * ad_s[j4 * 4 + 0] + v.y * ad_s[j4 * 4 + 1] +
              v.z * ad_s[j4 * 4 + 2] + v.w * ad_s[j4 * 4 + 3];
    }
    g_as[row] = ds;
    g_ad[row] = dd;
}

// ---------------------------------------------------------------------------
// Aggregation: one warp per destination node.
// ACT: 0 = bias + ReLU (D==64), 1 = bias + log_softmax (D==40, final layer)
// ---------------------------------------------------------------------------

template <int D, int ACT>
__global__ __launch_bounds__(256)
void aggregate_kernel(const float* __restrict__ h,
                      const float* __restrict__ bias,
                      float* __restrict__ out,
                      int N) {
    int gw = (blockIdx.x * blockDim.x + threadIdx.x) >> 5;
    int lane = threadIdx.x & 31;
    if (gw >= N) return;

    int beg = g_off[gw];
    int end = g_off[gw + 1];
    float ad = g_ad[gw];

    // ---- pass 1: online max + sum(exp) per lane, then warp combine
    // FINITE sentinel: exp(NEG_BIG - x) underflows to 0, never NaN.
    float m = NEG_BIG, s = 0.0f;
    for (int j = beg + lane; j < end; j += 32) {
        int sv = g_csr[j];
        float e = g_as[sv] + ad;
        e = (e > 0.0f) ? e : 0.2f * e;
        float nm = fmaxf(m, e);
        s = s * __expf(m - nm) + __expf(e - nm);
        m = nm;
    }
#pragma unroll
    for (int off = 16; off; off >>= 1) {
        float om = __shfl_xor_sync(0xffffffffu, m, off);
        float os = __shfl_xor_sync(0xffffffffu, s, off);
        float nm = fmaxf(m, om);
        s = s * __expf(m - nm) + os * __expf(om - nm);
        m = nm;
    }
    // every dst has its self-loop -> s > 0, m finite

    // ---- pass 2: weighted gather-sum
    float acc0 = 0.0f, acc1 = 0.0f;
    const bool has2 = (D == 64) || (lane < D - 32);
    for (int base = beg; base < end; base += 32) {
        int j = base + lane;
        int sv = 0;
        float w = 0.0f;
        if (j < end) {
            sv = g_csr[j];
            float e = g_as[sv] + ad;
            e = (e > 0.0f) ? e : 0.2f * e;
            w = __expf(e - m);
        }
        int cnt = min(32, end - base);
        for (int k = 0; k < cnt; k++) {
            int ss = __shfl_sync(0xffffffffu, sv, k);
            float ww = __shfl_sync(0xffffffffu, w, k);
            const float* hr = h + (size_t)ss * D;
            acc0 += ww * __ldg(hr + lane);
            if (has2) acc1 += ww * __ldg(hr + lane + 32);
        }
    }

    float inv = 1.0f / s;
    if (ACT == 0) {
        float v0 = fmaxf(acc0 * inv + __ldg(bias + lane), 0.0f);
        float v1 = fmaxf(acc1 * inv + __ldg(bias + lane + 32), 0.0f);
        out[(size_t)gw * D + lane] = v0;
        out[(size_t)gw * D + lane + 32] = v1;
    } else {
        // D == 40: bias + log_softmax (lanes 0..31 = ch 0..31; lanes 0..7 also ch 32..39)
        float v0 = acc0 * inv + __ldg(bias + lane);
        float v1 = has2 ? (acc1 * inv + __ldg(bias + lane + 32)) : NEG_BIG;
        float lm = fmaxf(v0, v1);
#pragma unroll
        for (int off = 16; off; off >>= 1)
            lm = fmaxf(lm, __shfl_xor_sync(0xffffffffu, lm, off));
        float ls = __expf(v0 - lm) + (has2 ? __expf(v1 - lm) : 0.0f);
#pragma unroll
        for (int off = 16; off; off >>= 1)
            ls += __shfl_xor_sync(0xffffffffu, ls, off);
        float L = lm + __logf(ls);
        out[(size_t)gw * D + lane] = v0 - L;
        if (has2) out[(size_t)gw * D + lane + 32] = v1 - L;
    }
}

// ---------------------------------------------------------------------------
// Host launcher
// ---------------------------------------------------------------------------

extern "C" void kernel_launch(void* const* d_in, const int* in_sizes, int n_in,
                              void* d_out, int out_size) {
    const float* x    = (const float*)d_in[0];
    const int*   ei   = (const int*)d_in[1];   // int32: JAX x64-disabled
    const float* W0   = (const float*)d_in[2];
    const float* as0  = (const float*)d_in[3];
    const float* ad0  = (const float*)d_in[4];
    const float* b0   = (const float*)d_in[5];
    const float* W1   = (const float*)d_in[6];
    const float* as1  = (const float*)d_in[7];
    const float* ad1  = (const float*)d_in[8];
    const float* b1   = (const float*)d_in[9];
    const float* W2   = (const float*)d_in[10];
    const float* as2  = (const float*)d_in[11];
    const float* ad2  = (const float*)d_in[12];
    const float* b2   = (const float*)d_in[13];
    float* out = (float*)d_out;

    int N = in_sizes[0] / 64;
    int E = in_sizes[1] / 2;
    int EL = E + N;

    float* hA;
    float* hB;
    cudaGetSymbolAddress((void**)&hA, g_hA);
    cudaGetSymbolAddress((void**)&hB, g_hB);

    // CSR build (per launch; structure shared by all 3 layers)
    zero_deg_kernel<<<(N + 255) / 256, 256>>>(N);
    count_edges_kernel<<<(EL + 255) / 256, 256>>>(ei, E, N);
    scan_offsets_kernel<<<1, 1024>>>(N);
    scatter_edges_kernel<<<(EL + 255) / 256, 256>>>(ei, E, N);

    int gemm_grid = (N + 127) / 128;
    int agg_grid = (N + 7) / 8;  // 8 warps / block

    // layer 0
    gemm_alpha_kernel<64, 64><<<gemm_grid, 128>>>(x, W0, as0, ad0, hA, N);
    aggregate_kernel<64, 0><<<agg_grid, 256>>>(hA, b0, hB, N);
    // layer 1
    gemm_alpha_kernel<64, 64><<<gemm_grid, 128>>>(hB, W1, as1, ad1, hA, N);
    aggregate_kernel<64, 0><<<agg_grid, 256>>>(hA, b1, hB, N);
    // layer 2 (+ fused log_softmax)
    gemm_alpha_kernel<64, 40><<<gemm_grid, 128>>>(hB, W2, as2, ad2, hA, N);
    aggregate_kernel<40, 1><<<agg_grid, 256>>>(hA, b2, out, N);
}